// round 2
// baseline (speedup 1.0000x reference)
#include <cuda_runtime.h>

// Problem: B=1, L=768, D_SINGLE=384, D_PAIR=128
//   left  = s @ W[:384]    (768x128)
//   right = s @ W[384:]    (768x128)
//   out[i,j,f] = left[i,f] + right[j,f] + bias[f]   -> 768*768*128 fp32 = 302 MB
//
// Inputs (metadata order): s (768*384 f32), z (unused!), W (768*128 f32), bias (128 f32)

#define L_DIM 768
#define DS 384
#define DP 128
#define TI 8          // M-rows per GEMM block

// scratch (no cudaMalloc allowed)
__device__ float g_left[L_DIM * DP];
__device__ float g_right[L_DIM * DP];

// ---------------------------------------------------------------------------
// Kernel 1: compute left and right projections.
// grid = L/TI = 96 blocks, 256 threads. Thread f in [0,256): f<128 -> left col f,
// f>=128 -> right col f-128. Register accumulators over TI rows.
// ---------------------------------------------------------------------------
__global__ __launch_bounds__(256) void proj_kernel(
    const float* __restrict__ s,    // [768, 384]
    const float* __restrict__ W)    // [768, 128]  (W1 rows 0..383, W2 rows 384..767)
{
    __shared__ float s_sh[TI][DS];
    const int i0 = blockIdx.x * TI;
    const int tid = threadIdx.x;

    // cooperative load of TI rows of s: TI*384 = 3072 floats, 256 threads -> 12 each
    for (int idx = tid; idx < TI * DS; idx += 256) {
        int r = idx / DS, c = idx % DS;
        s_sh[r][c] = s[(size_t)(i0 + r) * DS + c];
    }
    __syncthreads();

    const int f    = tid & 127;
    const int half = tid >> 7;                  // 0 = left, 1 = right
    const float* Wcol = W + (size_t)(half ? DS : 0) * DP + f;

    float acc[TI];
#pragma unroll
    for (int ii = 0; ii < TI; ii++) acc[ii] = 0.f;

    for (int k = 0; k < DS; k++) {
        float w = Wcol[(size_t)k * DP];         // coalesced across the 128 f-threads
#pragma unroll
        for (int ii = 0; ii < TI; ii++)
            acc[ii] = fmaf(s_sh[ii][k], w, acc[ii]);   // s_sh broadcast, no conflicts
    }

    float* dst = half ? g_right : g_left;
#pragma unroll
    for (int ii = 0; ii < TI; ii++)
        dst[(size_t)(i0 + ii) * DP + f] = acc[ii];
}

// ---------------------------------------------------------------------------
// Kernel 2: broadcast-add. out[i,j,f] = left[i,f] + right[j,f] + bias[f].
// grid = (6 j-chunks of 128, 768 i). 256 threads: f4 = tid&31 (32 float4 per row),
// jl = tid>>5 (8 parallel j rows), 16 j-iterations per thread.
// left+bias hoisted to registers; right L2-resident; streaming float4 stores.
// ---------------------------------------------------------------------------
__global__ __launch_bounds__(256) void bcast_kernel(
    const float* __restrict__ bias, // [128]
    float* __restrict__ out)        // [768,768,128]
{
    const int i  = blockIdx.y;
    const int j0 = blockIdx.x * 128;
    const int tid = threadIdx.x;
    const int f4 = tid & 31;
    const int jl = tid >> 5;

    const float4* left4  = reinterpret_cast<const float4*>(g_left);
    const float4* right4 = reinterpret_cast<const float4*>(g_right);
    const float4* bias4  = reinterpret_cast<const float4*>(bias);
    float4* out4 = reinterpret_cast<float4*>(out);

    float4 lv = left4[(size_t)i * 32 + f4];
    float4 bv = __ldg(bias4 + f4);
    lv.x += bv.x; lv.y += bv.y; lv.z += bv.z; lv.w += bv.w;

    const size_t orow = ((size_t)i * L_DIM + j0) * 32 + f4;  // in float4 units

#pragma unroll 4
    for (int jj = jl; jj < 128; jj += 8) {
        float4 rv = __ldg(right4 + (size_t)(j0 + jj) * 32 + f4);
        float4 o;
        o.x = lv.x + rv.x;
        o.y = lv.y + rv.y;
        o.z = lv.z + rv.z;
        o.w = lv.w + rv.w;
        __stcs(out4 + orow + (size_t)jj * 32, o);   // streaming store: don't pollute L2
    }
}

// ---------------------------------------------------------------------------
extern "C" void kernel_launch(void* const* d_in, const int* in_sizes, int n_in,
                              void* d_out, int out_size)
{
    const float* s    = (const float*)d_in[0];
    // d_in[1] = z : intentionally unused (reference never reads it)
    const float* W    = (const float*)d_in[2];
    const float* bias = (const float*)d_in[3];
    float* out = (float*)d_out;

    proj_kernel<<<L_DIM / TI, 256>>>(s, W);
    dim3 grid(L_DIM / 128, L_DIM);   // (6, 768)
    bcast_kernel<<<grid, 256>>>(bias, out);
}

// round 3
// speedup vs baseline: 1.0897x; 1.0897x over previous
#include <cuda_runtime.h>

// Problem: B=1, L=768, D_SINGLE=384, D_PAIR=128
//   left  = s @ W[:384] + bias   (768x128)   [bias folded in here]
//   right = s @ W[384:]          (768x128)
//   out[i,j,f] = left[i,f] + right[j,f]      -> 768*768*128 fp32 = 302 MB
//
// Inputs (metadata order): s (768*384 f32), z (UNUSED), W (768*128 f32), bias (128 f32)

#define L_DIM 768
#define DS 384
#define DP 128
#define TI 6          // rows per GEMM block -> 768/6 = 128 blocks (one wave on 148 SMs)

// scratch (no cudaMalloc allowed)
__device__ float g_left[L_DIM * DP];    // includes bias
__device__ float g_right[L_DIM * DP];

// ---------------------------------------------------------------------------
// Kernel 1: projections. grid = 128 blocks x 256 threads.
// Thread tid: f = tid&127 selects output column, half = tid>>7 selects left/right.
// s staged in smem, read back as float4 (4 k-values per LDS, warp-broadcast).
// W read as scalar LDG, fully coalesced across the 128 f-threads (L1/L2 hot).
// ---------------------------------------------------------------------------
__global__ __launch_bounds__(256) void proj_kernel(
    const float* __restrict__ s,     // [768, 384]
    const float* __restrict__ W,     // [768, 128]
    const float* __restrict__ bias)  // [128]
{
    __shared__ float s_sh[TI][DS];
    const int i0  = blockIdx.x * TI;
    const int tid = threadIdx.x;

    // cooperative load: TI*384 = 2304 floats / 256 threads = 9 each, coalesced
    for (int idx = tid; idx < TI * DS; idx += 256) {
        int r = idx / DS, c = idx % DS;
        s_sh[r][c] = s[(size_t)(i0 + r) * DS + c];
    }
    __syncthreads();

    const int f    = tid & 127;
    const int half = tid >> 7;                    // 0 = left, 1 = right
    const float* Wcol = W + (size_t)(half ? DS : 0) * DP + f;

    float acc[TI];
#pragma unroll
    for (int ii = 0; ii < TI; ii++) acc[ii] = 0.f;

    const float4 (*s4)[DS / 4] = reinterpret_cast<const float4 (*)[DS / 4]>(s_sh);

#pragma unroll 4
    for (int k4 = 0; k4 < DS / 4; k4++) {
        const int kb = k4 * 4;
        float w0 = Wcol[(size_t)(kb + 0) * DP];
        float w1 = Wcol[(size_t)(kb + 1) * DP];
        float w2 = Wcol[(size_t)(kb + 2) * DP];
        float w3 = Wcol[(size_t)(kb + 3) * DP];
#pragma unroll
        for (int ii = 0; ii < TI; ii++) {
            float4 sv = s4[ii][k4];               // one LDS.128, warp-broadcast
            acc[ii] = fmaf(sv.x, w0, acc[ii]);
            acc[ii] = fmaf(sv.y, w1, acc[ii]);
            acc[ii] = fmaf(sv.z, w2, acc[ii]);
            acc[ii] = fmaf(sv.w, w3, acc[ii]);
        }
    }

    if (half == 0) {
        const float b = bias[f];
#pragma unroll
        for (int ii = 0; ii < TI; ii++)
            g_left[(size_t)(i0 + ii) * DP + f] = acc[ii] + b;   // bias folded in
    } else {
#pragma unroll
        for (int ii = 0; ii < TI; ii++)
            g_right[(size_t)(i0 + ii) * DP + f] = acc[ii];
    }
}

// ---------------------------------------------------------------------------
// Kernel 2: broadcast-add. out[i,j,f] = left[i,f] + right[j,f].
// grid = (6 j-chunks of 128, 768 i). 256 threads: f4 = tid&31, jl = tid>>5.
// Per jj-step the 8 warps cover 8 consecutive j rows = one contiguous 4KB write.
// Streaming float4 stores keep the 302MB write stream from thrashing L2.
// ---------------------------------------------------------------------------
__global__ __launch_bounds__(256) void bcast_kernel(float* __restrict__ out)
{
    const int i   = blockIdx.y;
    const int j0  = blockIdx.x * 128;
    const int tid = threadIdx.x;
    const int f4  = tid & 31;
    const int jl  = tid >> 5;

    const float4* left4  = reinterpret_cast<const float4*>(g_left);
    const float4* right4 = reinterpret_cast<const float4*>(g_right);
    float4* out4 = reinterpret_cast<float4*>(out);

    const float4 lv = left4[(size_t)i * 32 + f4];       // already includes bias
    const size_t orow = ((size_t)i * L_DIM + j0) * 32 + f4;

#pragma unroll 4
    for (int jj = jl; jj < 128; jj += 8) {
        float4 rv = __ldg(right4 + (size_t)(j0 + jj) * 32 + f4);
        float4 o;
        o.x = lv.x + rv.x;
        o.y = lv.y + rv.y;
        o.z = lv.z + rv.z;
        o.w = lv.w + rv.w;
        __stcs(out4 + orow + (size_t)jj * 32, o);
    }
}

// ---------------------------------------------------------------------------
extern "C" void kernel_launch(void* const* d_in, const int* in_sizes, int n_in,
                              void* d_out, int out_size)
{
    const float* s    = (const float*)d_in[0];
    // d_in[1] = z : intentionally unused (reference never reads it)
    const float* W    = (const float*)d_in[2];
    const float* bias = (const float*)d_in[3];
    float* out = (float*)d_out;

    proj_kernel<<<L_DIM / TI, 256>>>(s, W, bias);
    dim3 grid(L_DIM / 128, L_DIM);   // (6, 768)
    bcast_kernel<<<grid, 256>>>(out);
}